// round 2
// baseline (speedup 1.0000x reference)
#include <cuda_runtime.h>
#include <math.h>

#define N_TOK 8192
#define E_NUM 16
#define TOPK 2
#define DIN 1024
#define DHID 4096
#define DOUT 1024
#define NP (N_TOK * TOPK)   // 16384 token-expert pairs
#define MAXT 288            // max M-tiles (<= 16384/64 + 16 = 272)

// Output layout (flattened tuple, float32):
//   [0, N*DOUT)                      final_output
//   [N*DOUT, +N*E)                   gating_logits
//   [N*DOUT + N*E, +N*TOPK)          indices (as float)
#define OUT_GL ((size_t)N_TOK * DOUT)
#define OUT_IDX (OUT_GL + (size_t)N_TOK * E_NUM)
#define OUT_TOTAL (OUT_IDX + (size_t)N_TOK * TOPK)

// ---------------- device scratch (no allocations allowed) ----------------
__device__ float g_h[(size_t)NP * DHID];    // 256 MB: relu(xW1+b1), sorted order
__device__ float g_yw[(size_t)NP * DOUT];   // 64 MB: weight * (hW2+b2), per pair
__device__ int   g_sorted[NP];              // pair ids grouped by expert
__device__ int   g_eid[NP];                 // expert id per pair
__device__ float g_wt[NP];                  // softmax weight per pair
__device__ int   g_cnt[E_NUM];
__device__ int   g_cur[E_NUM];
__device__ int   g_off[E_NUM + 1];
__device__ int   g_tile_e[MAXT];
__device__ int   g_tile_r[MAXT];
__device__ int   g_ntiles;

// ---------------- reset ----------------
__global__ void k_reset() {
    int t = threadIdx.x;
    if (t < E_NUM) { g_cnt[t] = 0; g_cur[t] = 0; }
    if (t == 0) g_ntiles = 0;
}

// ---------------- gating: logits, top-2, softmax ----------------
// block = 256 threads = 16 tokens x 16 experts
__global__ void k_gating(const float* __restrict__ x,
                         const float* __restrict__ Wg,
                         const float* __restrict__ bg,
                         const float* __restrict__ bias,
                         float* __restrict__ out,
                         int write_extra) {
    __shared__ float sx[16][256];
    __shared__ float slog[16][16];
    __shared__ float sbias[16];

    int tid = threadIdx.x;
    int tl = tid >> 4;          // local token 0..15
    int e  = tid & 15;          // expert 0..15
    int tok0 = blockIdx.x * 16;
    int token = tok0 + tl;

    if (tid < E_NUM) sbias[tid] = bias[tid];

    float acc = 0.f;
    for (int k0 = 0; k0 < DIN; k0 += 256) {
        __syncthreads();
        // load 16x256 floats (4096) cooperatively, float4
        #pragma unroll
        for (int i = 0; i < 4; i++) {
            int lin4 = i * 1024 + tid * 4;      // element index 0..4095 step 4
            int row = lin4 >> 8;                // /256
            int col = lin4 & 255;
            *(float4*)&sx[row][col] =
                *(const float4*)(x + (size_t)(tok0 + row) * DIN + k0 + col);
        }
        __syncthreads();
        #pragma unroll 8
        for (int k = 0; k < 256; k++)
            acc += sx[tl][k] * Wg[(size_t)(k0 + k) * E_NUM + e];
    }
    acc += bg[e];

    if (write_extra)
        out[OUT_GL + (size_t)token * E_NUM + e] = acc;
    slog[tl][e] = acc;
    __syncthreads();

    if (e == 0) {
        // top-2 on biased logits (first occurrence wins ties, like lax.top_k)
        float b0 = -INFINITY; int i0 = 0;
        #pragma unroll
        for (int j = 0; j < E_NUM; j++) {
            float v = slog[tl][j] + sbias[j];
            if (v > b0) { b0 = v; i0 = j; }
        }
        float b1v = -INFINITY; int i1 = 0;
        #pragma unroll
        for (int j = 0; j < E_NUM; j++) {
            if (j == i0) continue;
            float v = slog[tl][j] + sbias[j];
            if (v > b1v) { b1v = v; i1 = j; }
        }
        // softmax over raw gating logits at (i0, i1)
        float l0 = slog[tl][i0], l1 = slog[tl][i1];
        float m = fmaxf(l0, l1);
        float e0 = expf(l0 - m), e1 = expf(l1 - m);
        float inv = 1.f / (e0 + e1);
        float w0 = e0 * inv, w1 = e1 * inv;

        int p0 = token * 2, p1 = token * 2 + 1;
        g_eid[p0] = i0; g_wt[p0] = w0;
        g_eid[p1] = i1; g_wt[p1] = w1;
        atomicAdd(&g_cnt[i0], 1);
        atomicAdd(&g_cnt[i1], 1);
        if (write_extra) {
            out[OUT_IDX + p0] = (float)i0;
            out[OUT_IDX + p1] = (float)i1;
        }
    }
}

// ---------------- scan + tile map (tiny, 1 thread) ----------------
__global__ void k_scan() {
    int off = 0;
    g_off[0] = 0;
    for (int e = 0; e < E_NUM; e++) { off += g_cnt[e]; g_off[e + 1] = off; }
    int nt = 0;
    for (int e = 0; e < E_NUM; e++)
        for (int r = 0; r < g_cnt[e]; r += 64) {
            g_tile_e[nt] = e; g_tile_r[nt] = r; nt++;
        }
    g_ntiles = nt;
}

// ---------------- scatter pairs into expert-sorted order ----------------
__global__ void k_scatter() {
    int p = blockIdx.x * 256 + threadIdx.x;
    if (p >= NP) return;
    int e = g_eid[p];
    int pos = g_off[e] + atomicAdd(&g_cur[e], 1);
    g_sorted[pos] = p;
}

// ---------------- GEMM1: h = relu(gather(x) @ W1[e] + b1[e]) ----------------
// 64x64 tile, 256 threads, 4x4 micro-tile, K-step 16
__global__ void __launch_bounds__(256) k_gemm1(const float* __restrict__ x,
                                               const float* __restrict__ W1,
                                               const float* __restrict__ b1) {
    int tm = blockIdx.y;
    if (tm >= g_ntiles) return;
    int e = g_tile_e[tm], r0 = g_tile_r[tm];
    int base = g_off[e], cnt = g_cnt[e];
    int n0 = blockIdx.x * 64;

    __shared__ float As[16][68];   // [k][m], stride 68 keeps float4 alignment
    __shared__ float Bs[16][64];   // [k][n]
    __shared__ int s_tok[64];

    int tid = threadIdx.x;
    if (tid < 64) {
        int lr = r0 + tid;
        s_tok[tid] = (lr < cnt) ? (g_sorted[base + lr] >> 1) : -1;
    }
    __syncthreads();

    const float* Wb = W1 + (size_t)e * DIN * DHID;
    int tx = tid & 15, ty = tid >> 4;
    int arow = tid >> 2, akq = (tid & 3) * 4;    // A loader: row, k-quad
    int bnc = (tid & 15) * 4, bkr = tid >> 4;    // B loader: n-quad, k-row

    int tokA = s_tok[arow];
    const float* Arow = (tokA >= 0) ? (x + (size_t)tokA * DIN) : x;
    bool aValid = (tokA >= 0);

    float acc[4][4] = {};

    for (int k0 = 0; k0 < DIN; k0 += 16) {
        float4 av = aValid ? *(const float4*)(Arow + k0 + akq)
                           : make_float4(0.f, 0.f, 0.f, 0.f);
        float4 bv = *(const float4*)(Wb + (size_t)(k0 + bkr) * DHID + n0 + bnc);
        __syncthreads();
        As[akq + 0][arow] = av.x; As[akq + 1][arow] = av.y;
        As[akq + 2][arow] = av.z; As[akq + 3][arow] = av.w;
        *(float4*)&Bs[bkr][bnc] = bv;
        __syncthreads();
        #pragma unroll
        for (int kk = 0; kk < 16; kk++) {
            float4 af = *(const float4*)&As[kk][ty * 4];
            float4 bf = *(const float4*)&Bs[kk][tx * 4];
            float ar[4] = {af.x, af.y, af.z, af.w};
            float br[4] = {bf.x, bf.y, bf.z, bf.w};
            #pragma unroll
            for (int i = 0; i < 4; i++)
                #pragma unroll
                for (int j = 0; j < 4; j++)
                    acc[i][j] += ar[i] * br[j];
        }
    }

    float4 bb = *(const float4*)(b1 + (size_t)e * DHID + n0 + tx * 4);
    float bbs[4] = {bb.x, bb.y, bb.z, bb.w};
    #pragma unroll
    for (int i = 0; i < 4; i++) {
        int lr = r0 + ty * 4 + i;
        if (lr < cnt) {
            float4 v;
            v.x = fmaxf(acc[i][0] + bbs[0], 0.f);
            v.y = fmaxf(acc[i][1] + bbs[1], 0.f);
            v.z = fmaxf(acc[i][2] + bbs[2], 0.f);
            v.w = fmaxf(acc[i][3] + bbs[3], 0.f);
            *(float4*)(g_h + (size_t)(base + lr) * DHID + n0 + tx * 4) = v;
        }
    }
}

// ---------------- GEMM2: yw[pair] = wt[pair] * (h @ W2[e] + b2[e]) ----------------
__global__ void __launch_bounds__(256) k_gemm2(const float* __restrict__ W2,
                                               const float* __restrict__ b2) {
    int tm = blockIdx.y;
    if (tm >= g_ntiles) return;
    int e = g_tile_e[tm], r0 = g_tile_r[tm];
    int base = g_off[e], cnt = g_cnt[e];
    int n0 = blockIdx.x * 64;

    __shared__ float As[16][68];
    __shared__ float Bs[16][64];
    __shared__ int s_pair[64];

    int tid = threadIdx.x;
    if (tid < 64) {
        int lr = r0 + tid;
        s_pair[tid] = (lr < cnt) ? g_sorted[base + lr] : -1;
    }
    __syncthreads();

    const float* Wb = W2 + (size_t)e * DHID * DOUT;
    int tx = tid & 15, ty = tid >> 4;
    int arow = tid >> 2, akq = (tid & 3) * 4;
    int bnc = (tid & 15) * 4, bkr = tid >> 4;

    int lrA = r0 + arow;
    const float* Arow = g_h + (size_t)(base + ((lrA < cnt) ? lrA : 0)) * DHID;

    float acc[4][4] = {};

    for (int k0 = 0; k0 < DHID; k0 += 16) {
        float4 av = *(const float4*)(Arow + k0 + akq);
        float4 bv = *(const float4*)(Wb + (size_t)(k0 + bkr) * DOUT + n0 + bnc);
        __syncthreads();
        As[akq + 0][arow] = av.x; As[akq + 1][arow] = av.y;
        As[akq + 2][arow] = av.z; As[akq + 3][arow] = av.w;
        *(float4*)&Bs[bkr][bnc] = bv;
        __syncthreads();
        #pragma unroll
        for (int kk = 0; kk < 16; kk++) {
            float4 af = *(const float4*)&As[kk][ty * 4];
            float4 bf = *(const float4*)&Bs[kk][tx * 4];
            float ar[4] = {af.x, af.y, af.z, af.w};
            float br[4] = {bf.x, bf.y, bf.z, bf.w};
            #pragma unroll
            for (int i = 0; i < 4; i++)
                #pragma unroll
                for (int j = 0; j < 4; j++)
                    acc[i][j] += ar[i] * br[j];
        }
    }

    float4 bb = *(const float4*)(b2 + (size_t)e * DOUT + n0 + tx * 4);
    float bbs[4] = {bb.x, bb.y, bb.z, bb.w};
    #pragma unroll
    for (int i = 0; i < 4; i++) {
        int lr = r0 + ty * 4 + i;
        if (lr < cnt) {
            int pair = s_pair[ty * 4 + i];
            float w = g_wt[pair];
            float4 v;
            v.x = w * (acc[i][0] + bbs[0]);
            v.y = w * (acc[i][1] + bbs[1]);
            v.z = w * (acc[i][2] + bbs[2]);
            v.w = w * (acc[i][3] + bbs[3]);
            *(float4*)(g_yw + (size_t)pair * DOUT + n0 + tx * 4) = v;
        }
    }
}

// ---------------- combine: out[t] = yw[2t] + yw[2t+1] ----------------
__global__ void k_combine(float* __restrict__ out) {
    int i = blockIdx.x * 256 + threadIdx.x;           // float4 index
    const int C = DOUT / 4;                           // 256
    int t = i >> 8;
    int c = i & 255;
    const float4* yw = (const float4*)g_yw;
    float4 u = yw[(size_t)(2 * t) * C + c];
    float4 v = yw[(size_t)(2 * t + 1) * C + c];
    float4 r;
    r.x = u.x + v.x; r.y = u.y + v.y; r.z = u.z + v.z; r.w = u.w + v.w;
    ((float4*)out)[i] = r;
}

// ---------------- launch ----------------
extern "C" void kernel_launch(void* const* d_in, const int* in_sizes, int n_in,
                              void* d_out, int out_size) {
    const float* x    = (const float*)d_in[0];
    const float* Wg   = (const float*)d_in[1];
    const float* bg   = (const float*)d_in[2];
    const float* W1   = (const float*)d_in[3];
    const float* b1   = (const float*)d_in[4];
    const float* W2   = (const float*)d_in[5];
    const float* b2   = (const float*)d_in[6];
    const float* bias = (const float*)d_in[7];
    float* out = (float*)d_out;

    int write_extra = ((size_t)out_size >= OUT_TOTAL) ? 1 : 0;

    k_reset<<<1, 32>>>();
    k_gating<<<N_TOK / 16, 256>>>(x, Wg, bg, bias, out, write_extra);
    k_scan<<<1, 1>>>();
    k_scatter<<<NP / 256, 256>>>();
    k_gemm1<<<dim3(DHID / 64, MAXT), 256>>>(x, W1, b1);
    k_gemm2<<<dim3(DOUT / 64, MAXT), 256>>>(W2, b2);
    k_combine<<<(N_TOK * DOUT / 4) / 256, 256>>>(out);
}